// round 1
// baseline (speedup 1.0000x reference)
#include <cuda_runtime.h>
#include <cuda_bf16.h>

#define NB 4
#define D0 64
#define C1 64
#define C2 128
#define DS 32
#define NCELL (NB*DS*DS*DS)   // 131072

// ---------------- scratch (device globals; no allocation allowed) ----------
__device__ float g_hds[NCELL*C1];   // downsampled h       33.5 MB
__device__ float g_xds[NCELL*C1];   // downsampled x*m     33.5 MB
__device__ float g_m2 [NCELL];      // mask2 as float
__device__ float g_t1 [NCELL*C2];   // after conv1         67 MB
__device__ float g_t2 [NCELL*C2];   // after norm2+silu    67 MB
__device__ int   g_mask_mode;       // 0=int32/float32 word, 2=byte

// ---------------- mask dtype detection -------------------------------------
__global__ void k_detect(const unsigned int* __restrict__ m, int nwords)
{
    if (threadIdx.x == 0 && blockIdx.x == 0) {
        int mode = 0;
        for (int i = 0; i < nwords; i++) {
            unsigned w = m[i];
            if (w == 0u) continue;
            if (w == 1u)               mode = 0;   // int32 0/1
            else if (w == 0x3F800000u) mode = 0;   // float32 1.0 (nonzero word works too)
            else                       mode = 2;   // packed bytes
            break;
        }
        g_mask_mode = mode;
    }
}

__device__ __forceinline__ bool mask_at(const void* m, long v, int mode)
{
    if (mode == 2) return ((const unsigned char*)m)[v] != 0;
    return ((const unsigned int*)m)[v] != 0u;
}

// ---------------- K1: LN1 + affine + SiLU + mask + 2x downsample (h and x) -
__global__ void k_ln_ds(const float* __restrict__ feats, const void* __restrict__ mask,
                        const float* __restrict__ gamma, const float* __restrict__ beta)
{
    const int c  = threadIdx.x;             // 64 channels
    const int dx = blockIdx.x, dy = blockIdx.y;
    const int b  = blockIdx.z >> 5, dz = blockIdx.z & 31;
    const int mode = g_mask_mode;

    __shared__ float sh1[2], sh2[2];

    const float g  = gamma[c];
    const float be = beta[c];
    float hsum = 0.f, xsum = 0.f;
    int cnt = 0;

    #pragma unroll
    for (int s = 0; s < 8; s++) {
        const int z = 2*dz + (s >> 2);
        const int y = 2*dy + ((s >> 1) & 1);
        const int x = 2*dx + (s & 1);
        const long v = (((long)b*D0 + z)*D0 + y)*D0 + x;
        const bool act = mask_at(mask, v, mode);
        const float xv = feats[v*C1 + c];

        float a = xv, q = xv*xv;
        #pragma unroll
        for (int o = 16; o > 0; o >>= 1) {
            a += __shfl_xor_sync(0xffffffffu, a, o);
            q += __shfl_xor_sync(0xffffffffu, q, o);
        }
        const int w = c >> 5;
        if ((c & 31) == 0) { sh1[w] = a; sh2[w] = q; }
        __syncthreads();
        const float sa = sh1[0] + sh1[1];
        const float sq = sh2[0] + sh2[1];
        __syncthreads();

        const float mu  = sa * (1.f/64.f);
        const float var = sq * (1.f/64.f) - mu*mu;
        const float ln  = (xv - mu) * rsqrtf(var + 1e-6f);
        const float hh  = ln * g + be;
        const float sil = hh / (1.f + __expf(-hh));
        if (act) { hsum += sil; xsum += xv; cnt++; }
    }

    const long cell = (((long)b*DS + dz)*DS + dy)*DS + dx;
    const float inv = 1.f / (float)max(cnt, 1);
    g_hds[cell*C1 + c] = hsum * inv;
    g_xds[cell*C1 + c] = xsum * inv;
    if (c == 0) g_m2[cell] = (cnt > 0) ? 1.f : 0.f;
}

// ---------------- conv: dense SAME 3x3x3 conv, masked output ----------------
// One block per (b, dz, dy) row: 32 voxels x COUT outputs. threadIdx.x = co.
template<int CIN, int COUT>
__global__ void __launch_bounds__(128, 2)
k_conv(const float* __restrict__ in, const float* __restrict__ wgt,
       const float* __restrict__ bias, const float* __restrict__ m2,
       float* __restrict__ out)
{
    extern __shared__ float smem[];
    float* s_in = smem;              // [34][CIN]
    float* s_w  = smem + 34*CIN;     // [CIN][COUT]

    const int co = threadIdx.x;      // COUT == 128 == blockDim.x
    const int dy = blockIdx.x, dz = blockIdx.y, b = blockIdx.z;

    float acc[32];
    #pragma unroll
    for (int w = 0; w < 32; w++) acc[w] = 0.f;

    for (int kd = 0; kd < 3; kd++) {
        const int z = dz + kd - 1;
        if ((unsigned)z >= DS) continue;
        for (int kh = 0; kh < 3; kh++) {
            const int y = dy + kh - 1;
            if ((unsigned)y >= DS) continue;

            __syncthreads();   // previous tap finished with s_in
            const float* rowbase = in + ((((long)b*DS + z)*DS + y)*DS) * CIN;
            for (int i = co; i < 34*CIN; i += 128) {
                const int p  = i / CIN;
                const int ci = i - p*CIN;
                const int wi = p - 1;
                s_in[i] = ((unsigned)wi < DS) ? rowbase[(long)wi*CIN + ci] : 0.f;
            }

            for (int kw = 0; kw < 3; kw++) {
                __syncthreads();  // protect s_w reuse + s_in visibility
                const float4* wsrc = (const float4*)(wgt + ((long)((kd*3 + kh)*3 + kw)) * CIN * COUT);
                float4* wdst = (float4*)s_w;
                #pragma unroll 4
                for (int i = co; i < CIN*COUT/4; i += 128) wdst[i] = wsrc[i];
                __syncthreads();

                #pragma unroll 2
                for (int ci = 0; ci < CIN; ci++) {
                    const float wv = s_w[ci*COUT + co];
                    const float* ip = s_in + kw*CIN + ci;
                    #pragma unroll
                    for (int w = 0; w < 32; w++)
                        acc[w] += ip[w*CIN] * wv;
                }
            }
        }
    }

    const long cellbase = (((long)b*DS + dz)*DS + dy)*DS;
    const float bv = bias[co];
    #pragma unroll 4
    for (int w = 0; w < 32; w++) {
        const float m = m2[cellbase + w];
        out[(cellbase + w)*COUT + co] = (acc[w] + bv) * m;
    }
}

// ---------------- K3: LN2 (no affine) + SiLU + mask -------------------------
__global__ void k_norm2(const float* __restrict__ t1, const float* __restrict__ m2,
                        float* __restrict__ t2)
{
    const int c  = threadIdx.x;      // 128
    const int dx = blockIdx.x, dy = blockIdx.y;
    const int b  = blockIdx.z >> 5, dz = blockIdx.z & 31;
    const long cell = (((long)b*DS + dz)*DS + dy)*DS + dx;

    __shared__ float sh1[4], sh2[4];

    const float xv = t1[cell*C2 + c];
    float a = xv, q = xv*xv;
    #pragma unroll
    for (int o = 16; o > 0; o >>= 1) {
        a += __shfl_xor_sync(0xffffffffu, a, o);
        q += __shfl_xor_sync(0xffffffffu, q, o);
    }
    const int w = c >> 5;
    if ((c & 31) == 0) { sh1[w] = a; sh2[w] = q; }
    __syncthreads();
    const float sa = sh1[0] + sh1[1] + sh1[2] + sh1[3];
    const float sq = sh2[0] + sh2[1] + sh2[2] + sh2[3];

    const float mu  = sa * (1.f/128.f);
    const float var = sq * (1.f/128.f) - mu*mu;
    const float ln  = (xv - mu) * rsqrtf(var + 1e-6f);
    const float sil = ln / (1.f + __expf(-ln));
    t2[cell*C2 + c] = sil * m2[cell];
}

// ---------------- K5: skip linear (64->128) + bias + mask, fused add --------
__global__ void __launch_bounds__(128)
k_skip(const float* __restrict__ xds, const float* __restrict__ wsk,
       const float* __restrict__ bsk, const float* __restrict__ m2,
       float* __restrict__ out)
{
    __shared__ float s_w[C1*C2];     // 32 KB
    __shared__ float s_x[32*C1];     // 8 KB

    const int co = threadIdx.x;
    const int dy = blockIdx.x, dz = blockIdx.y, b = blockIdx.z;
    const long cellbase = (((long)b*DS + dz)*DS + dy)*DS;

    {
        const float4* ws = (const float4*)wsk;
        float4* wd = (float4*)s_w;
        #pragma unroll 4
        for (int i = co; i < C1*C2/4; i += 128) wd[i] = ws[i];
        const float4* xs = (const float4*)(xds + cellbase*C1);
        float4* xd = (float4*)s_x;
        #pragma unroll
        for (int i = co; i < 32*C1/4; i += 128) xd[i] = xs[i];
    }
    __syncthreads();

    float acc[32];
    #pragma unroll
    for (int w = 0; w < 32; w++) acc[w] = 0.f;
    #pragma unroll 2
    for (int ci = 0; ci < C1; ci++) {
        const float wv = s_w[ci*C2 + co];
        #pragma unroll
        for (int w = 0; w < 32; w++)
            acc[w] += s_x[w*C1 + ci] * wv;
    }

    const float bv = bsk[co];
    #pragma unroll 4
    for (int w = 0; w < 32; w++) {
        const float m = m2[cellbase + w];
        const long i = (cellbase + w)*C2 + co;
        out[i] = (m != 0.f) ? (out[i] + acc[w] + bv) : 0.f;
    }
}

// ---------------- launch ----------------------------------------------------
extern "C" void kernel_launch(void* const* d_in, const int* in_sizes, int n_in,
                              void* d_out, int out_size)
{
    const float* feats = (const float*)d_in[0];
    const void*  mask  = d_in[1];
    const float* gamma1= (const float*)d_in[2];
    const float* beta1 = (const float*)d_in[3];
    const float* w1    = (const float*)d_in[4];
    const float* b1    = (const float*)d_in[5];
    const float* w2    = (const float*)d_in[6];
    const float* b2    = (const float*)d_in[7];
    const float* wsk   = (const float*)d_in[8];
    const float* bsk   = (const float*)d_in[9];
    float* out = (float*)d_out;

    float *p_hds, *p_xds, *p_m2, *p_t1, *p_t2;
    cudaGetSymbolAddress((void**)&p_hds, g_hds);
    cudaGetSymbolAddress((void**)&p_xds, g_xds);
    cudaGetSymbolAddress((void**)&p_m2,  g_m2);
    cudaGetSymbolAddress((void**)&p_t1,  g_t1);
    cudaGetSymbolAddress((void**)&p_t2,  g_t2);

    // Detect mask dtype (scan bound = element_count/4 words: safe for any width)
    k_detect<<<1, 32>>>((const unsigned int*)mask, in_sizes[1] / 4);

    // Stage A: LN1+SiLU+mask fused with 2x downsample of h and x*m
    dim3 gA(DS, DS, NB*DS);          // (dx, dy, b*32+dz)
    k_ln_ds<<<gA, C1>>>(feats, mask, gamma1, beta1);

    // conv1: 64 -> 128
    dim3 gC(DS, DS, NB);             // (dy, dz, b)
    size_t sm1 = (size_t)(34*C1 + C1*C2) * sizeof(float);    // ~41.5 KB
    k_conv<C1, C2><<<gC, 128, sm1>>>(p_hds, w1, b1, p_m2, p_t1);

    // norm2 + SiLU + mask
    k_norm2<<<gA, C2>>>(p_t1, p_m2, p_t2);

    // conv2: 128 -> 128 (needs >48KB dynamic smem)
    size_t sm2 = (size_t)(34*C2 + C2*C2) * sizeof(float);    // ~83 KB
    cudaFuncSetAttribute(k_conv<C2, C2>,
                         cudaFuncAttributeMaxDynamicSharedMemorySize, (int)sm2);
    k_conv<C2, C2><<<gC, 128, sm2>>>(p_t2, w2, b2, p_m2, out);

    // skip linear + fused add into out
    k_skip<<<gC, 128>>>(p_xds, wsk, bsk, p_m2, out);
}